// round 3
// baseline (speedup 1.0000x reference)
#include <cuda_runtime.h>
#include <float.h>

// Problem constants
#define B_   16
#define N_   2048
#define C_   128
#define M_   (B_ * N_)          // 32768 rows
#define KNN  8
#define NBLK 4

#define ALPHA_F    0.8888888888888888f   // 8/9
#define ONEMA_F    0.1111111111111111f   // 1/9
#define WEDGE_F    0.125f                // normalized adjacency entry (deg=8 everywhere)

typedef unsigned long long u64;

__device__ __forceinline__ void ffma2(u64 &acc, u64 a, u64 b) {
    asm("fma.rn.f32x2 %0, %1, %2, %0;" : "+l"(acc) : "l"(a), "l"(b));
}
__device__ __forceinline__ float2 unpack2(u64 v) {
    float2 f; asm("mov.b64 {%0, %1}, %2;" : "=f"(f.x), "=f"(f.y) : "l"(v)); return f;
}

// ---------------- scratch (static device globals; no allocs allowed) ---------
__device__ float g_pts[M_ * C_];
__device__ float g_Ya [M_ * C_];   // epilogue-fused: pts + alpha * relu(pts)@WcT
__device__ float g_Yg [M_ * C_];
__device__ float g_Uc [M_ * 6];
__device__ float g_Ug [M_ * 6];
__device__ int   g_nbr[M_ * KNN];  // [0]=self, [1..7]=kNN (within-batch indices)

// ---------------- 1) kNN top-8 (smallest dist, stable ties) ------------------
__global__ void knn_kernel(const float* __restrict__ xyz) {
    __shared__ float sx[N_], sy[N_], sz[N_], s2[N_];
    int b = blockIdx.x >> 3;
    int qBase = (blockIdx.x & 7) * 256;
    const float* X = xyz + (size_t)b * 3 * N_;
    for (int i = threadIdx.x; i < N_; i += 256) {
        float x = X[i], y = X[N_ + i], z = X[2 * N_ + i];
        sx[i] = x; sy[i] = y; sz[i] = z;
        s2[i] = x * x + y * y + z * z;
    }
    __syncthreads();

    int q = qBase + threadIdx.x;
    float qx = sx[q], qy = sy[q], qz = sz[q], q2 = s2[q];
    float bd[KNN]; int bi[KNN];
#pragma unroll
    for (int s = 0; s < KNN; ++s) { bd[s] = FLT_MAX; bi[s] = 0x7fffffff; }

    for (int j = 0; j < N_; ++j) {
        float inner = qx * sx[j] + qy * sy[j] + qz * sz[j];
        float d = (q2 + s2[j]) - 2.0f * inner;
        if (d < bd[KNN - 1]) {                   // strict <: stable tie (lower idx wins)
            bd[KNN - 1] = d; bi[KNN - 1] = j;
#pragma unroll
            for (int s = KNN - 1; s > 0; --s) {
                if (bd[s] < bd[s - 1]) {
                    float td = bd[s]; bd[s] = bd[s - 1]; bd[s - 1] = td;
                    int   ti = bi[s]; bi[s] = bi[s - 1]; bi[s - 1] = ti;
                }
            }
        }
    }
    int* outp = g_nbr + (size_t)(b * N_ + q) * KNN;
    outp[0] = q;
#pragma unroll
    for (int s = 1; s < KNN; ++s) outp[s] = bi[s];
}

// ------- 2) transpose points (B,C,N) -> pts (B,N,C), half the batch per call -
__global__ void transpose_in(const float* __restrict__ pin, int bOff) {
    __shared__ float tile[32][33];
    int b = blockIdx.z + bOff;
    int n0 = blockIdx.x * 32, c0 = blockIdx.y * 32;
    const float* src = pin + (size_t)b * C_ * N_;
    float* dst = g_pts + (size_t)b * N_ * C_;
    for (int r = threadIdx.y; r < 32; r += 8)
        tile[r][threadIdx.x] = src[(c0 + r) * N_ + n0 + threadIdx.x];
    __syncthreads();
    for (int r = threadIdx.y; r < 32; r += 8)
        dst[(n0 + r) * C_ + c0 + threadIdx.x] = tile[threadIdx.x][r];
}

// ---------------- 3) single-matrix SGEMM via packed fma.rn.f32x2 -------------
// gridDim.y == 2:
//   y=0:  Ya = pts + ALPHA * (relu(pts) @ WcT)     (residual fused in epilogue)
//   y=1:  Yg = pts @ WgT
// BM=128 rows/block, BN=128 (all cols), BK=16, 256 threads, 2 CTAs/SM.
// Per thread: 8 rows x 8 cols -> 32 packed u64 accumulators.
// A stored in smem pre-duplicated (a,a) (relu pre-applied for y=0), so the
// inner loop is 6 LDS.128 + 32 FFMA2 per kk -> FMA-pipe bound.
#define BM 128
#define BK 16
__global__ __launch_bounds__(256, 2) void gemm_one(const float* __restrict__ Wc,
                                                   const float* __restrict__ Wg) {
    __shared__ float2 sA2[BK][BM];   // (a,a) pairs
    __shared__ float  sW [BK][C_];
    const bool doRelu = (blockIdx.y == 0);
    const float* __restrict__ W = doRelu ? Wc : Wg;
    const float* A = g_pts;
    int tid = threadIdx.x;
    int tx = tid & 15;          // cols tx*8 .. tx*8+7
    int ty = tid >> 4;          // rows ty*8 .. ty*8+7
    int row0 = blockIdx.x * BM;

    u64 acc[8][4];
#pragma unroll
    for (int i = 0; i < 8; ++i)
#pragma unroll
        for (int j = 0; j < 4; ++j) acc[i][j] = 0ull;

    for (int k0 = 0; k0 < C_; k0 += BK) {
        // A tile: 128x16 = 512 float4 -> 2 per thread (duplicated, relu'd if y=0)
#pragma unroll
        for (int r = 0; r < 2; ++r) {
            int idx = tid + r * 256;
            int m = idx >> 2;
            int kq = (idx & 3) * 4;
            float4 v = *(const float4*)&A[(size_t)(row0 + m) * C_ + k0 + kq];
            if (doRelu) {
                v.x = fmaxf(v.x, 0.f); v.y = fmaxf(v.y, 0.f);
                v.z = fmaxf(v.z, 0.f); v.w = fmaxf(v.w, 0.f);
            }
            sA2[kq + 0][m] = make_float2(v.x, v.x);
            sA2[kq + 1][m] = make_float2(v.y, v.y);
            sA2[kq + 2][m] = make_float2(v.z, v.z);
            sA2[kq + 3][m] = make_float2(v.w, v.w);
        }
        // W tile: 128x16 = 512 float4 -> 2 per thread
#pragma unroll
        for (int r = 0; r < 2; ++r) {
            int idx = tid + r * 256;
            int d = idx >> 2;
            int kq = (idx & 3) * 4;
            float4 vw = *(const float4*)&W[d * C_ + k0 + kq];
            sW[kq + 0][d] = vw.x; sW[kq + 1][d] = vw.y;
            sW[kq + 2][d] = vw.z; sW[kq + 3][d] = vw.w;
        }
        __syncthreads();
#pragma unroll
        for (int kk = 0; kk < BK; ++kk) {
            ulonglong2 a01 = *(const ulonglong2*)&sA2[kk][ty * 8 + 0];
            ulonglong2 a23 = *(const ulonglong2*)&sA2[kk][ty * 8 + 2];
            ulonglong2 a45 = *(const ulonglong2*)&sA2[kk][ty * 8 + 4];
            ulonglong2 a67 = *(const ulonglong2*)&sA2[kk][ty * 8 + 6];
            u64 ap[8] = {a01.x, a01.y, a23.x, a23.y, a45.x, a45.y, a67.x, a67.y};
            ulonglong2 wq0 = *(const ulonglong2*)&sW[kk][tx * 8 + 0];
            ulonglong2 wq1 = *(const ulonglong2*)&sW[kk][tx * 8 + 4];
            u64 w[4] = {wq0.x, wq0.y, wq1.x, wq1.y};
#pragma unroll
            for (int i = 0; i < 8; ++i)
#pragma unroll
                for (int j = 0; j < 4; ++j)
                    ffma2(acc[i][j], ap[i], w[j]);
        }
        __syncthreads();
    }
    // epilogue
    if (doRelu) {
#pragma unroll
        for (int i = 0; i < 8; ++i) {
            size_t base = (size_t)(row0 + ty * 8 + i) * C_ + tx * 8;
            float4 p0 = *(const float4*)&g_pts[base];
            float4 p1 = *(const float4*)&g_pts[base + 4];
            float2 c0 = unpack2(acc[i][0]), c1 = unpack2(acc[i][1]);
            float2 c2 = unpack2(acc[i][2]), c3 = unpack2(acc[i][3]);
            *(float4*)&g_Ya[base] =
                make_float4(p0.x + ALPHA_F * c0.x, p0.y + ALPHA_F * c0.y,
                            p0.z + ALPHA_F * c1.x, p0.w + ALPHA_F * c1.y);
            *(float4*)&g_Ya[base + 4] =
                make_float4(p1.x + ALPHA_F * c2.x, p1.y + ALPHA_F * c2.y,
                            p1.z + ALPHA_F * c3.x, p1.w + ALPHA_F * c3.y);
        }
    } else {
#pragma unroll
        for (int i = 0; i < 8; ++i) {
            size_t base = (size_t)(row0 + ty * 8 + i) * C_ + tx * 8;
            float2 g0 = unpack2(acc[i][0]), g1 = unpack2(acc[i][1]);
            float2 g2 = unpack2(acc[i][2]), g3 = unpack2(acc[i][3]);
            *(float4*)&g_Yg[base]     = make_float4(g0.x, g0.y, g1.x, g1.y);
            *(float4*)&g_Yg[base + 4] = make_float4(g2.x, g2.y, g3.x, g3.y);
        }
    }
}

// ------- 4) gather + residual: pts = Ya + (1-a)*(adj@Yg) ---------------------
__global__ void gather_combine() {
    int node = blockIdx.x * 8 + (threadIdx.x >> 5);
    int lane = threadIdx.x & 31;
    int base = node & ~(N_ - 1);                  // batch start row
    const int* nb = g_nbr + (size_t)node * KNN;
    int c = lane * 4;
    float4 acc = make_float4(0.f, 0.f, 0.f, 0.f);
#pragma unroll
    for (int s = 0; s < KNN; ++s) {
        const float4 v = *(const float4*)&g_Yg[(size_t)(base + nb[s]) * C_ + c];
        acc.x += v.x; acc.y += v.y; acc.z += v.z; acc.w += v.w;
    }
    float4 ya = *(const float4*)&g_Ya[(size_t)node * C_ + c];
    float4 o;
    o.x = ya.x + ONEMA_F * (WEDGE_F * acc.x);
    o.y = ya.y + ONEMA_F * (WEDGE_F * acc.y);
    o.z = ya.z + ONEMA_F * (WEDGE_F * acc.z);
    o.w = ya.w + ONEMA_F * (WEDGE_F * acc.w);
    *(float4*)&g_pts[(size_t)node * C_ + c] = o;
}

// ------- 5) unpool projection: Uc = pts@WucT, Ug = pts@WugT (6 outs each) ----
__global__ void unpool_proj(const float* __restrict__ Wuc,
                            const float* __restrict__ Wug) {
    __shared__ float swc[6 * C_], swg[6 * C_];
    for (int i = threadIdx.x; i < 6 * C_; i += 256) { swc[i] = Wuc[i]; swg[i] = Wug[i]; }
    __syncthreads();
    int node = blockIdx.x * 8 + (threadIdx.x >> 5);
    int lane = threadIdx.x & 31;
    float4 p = *(const float4*)&g_pts[(size_t)node * C_ + lane * 4];
#pragma unroll
    for (int o = 0; o < 6; ++o) {
        float4 wc = *(const float4*)&swc[o * C_ + lane * 4];
        float4 wg = *(const float4*)&swg[o * C_ + lane * 4];
        float dc = p.x * wc.x + p.y * wc.y + p.z * wc.z + p.w * wc.w;
        float dg = p.x * wg.x + p.y * wg.y + p.z * wg.z + p.w * wg.w;
#pragma unroll
        for (int off = 16; off; off >>= 1) {
            dc += __shfl_xor_sync(0xffffffffu, dc, off);
            dg += __shfl_xor_sync(0xffffffffu, dg, off);
        }
        if (lane == 0) {
            g_Uc[(size_t)node * 6 + o] = dc;
            g_Ug[(size_t)node * 6 + o] = dg;
        }
    }
}

// ------- 6) finalize new_xyz: a*Uc + (1-a)*(adj@Ug), fold + reshape ----------
__global__ void finalize_xyz(const float* __restrict__ xyz, float* __restrict__ out) {
    int node = blockIdx.x * 256 + threadIdx.x;        // 0..32767
    int b = node >> 11, n = node & (N_ - 1);
    int base = node & ~(N_ - 1);
    const int* nb = g_nbr + (size_t)node * KNN;
    float g[6] = {0.f, 0.f, 0.f, 0.f, 0.f, 0.f};
#pragma unroll
    for (int s = 0; s < KNN; ++s) {
        const float* r = g_Ug + (size_t)(base + nb[s]) * 6;
#pragma unroll
        for (int o = 0; o < 6; ++o) g[o] += r[o];
    }
#pragma unroll
    for (int o = 0; o < 6; ++o) {
        float v = ALPHA_F * g_Uc[(size_t)node * 6 + o] + ONEMA_F * (WEDGE_F * g[o]);
        int cdim = o >> 1, t = o & 1;
        out[(size_t)b * 3 * (2 * N_) + cdim * (2 * N_) + t * N_ + n] =
            v + xyz[(size_t)b * 3 * N_ + cdim * N_ + n];
    }
}

// ------- 7) transpose pts (B,N,C) -> output (B,C,N) --------------------------
__global__ void transpose_out(float* __restrict__ out) {
    __shared__ float tile[32][33];
    int b = blockIdx.z;
    int n0 = blockIdx.x * 32, c0 = blockIdx.y * 32;
    const float* src = g_pts + (size_t)b * N_ * C_;
    float* dst = out + (size_t)b * C_ * N_;
    for (int r = threadIdx.y; r < 32; r += 8)
        tile[r][threadIdx.x] = src[(n0 + r) * C_ + c0 + threadIdx.x];
    __syncthreads();
    for (int r = threadIdx.y; r < 32; r += 8)
        dst[(c0 + r) * N_ + n0 + threadIdx.x] = tile[threadIdx.x][r];
}

// -----------------------------------------------------------------------------
extern "C" void kernel_launch(void* const* d_in, const int* in_sizes, int n_in,
                              void* d_out, int out_size) {
    const float* xyz    = (const float*)d_in[0];   // (16,3,2048)
    const float* points = (const float*)d_in[1];   // (16,128,2048)
    const float* Wc     = (const float*)d_in[2];   // (4,128,128)
    const float* Wg     = (const float*)d_in[3];   // (4,128,128)
    const float* Wuc    = (const float*)d_in[4];   // (6,128)
    const float* Wug    = (const float*)d_in[5];   // (6,128)
    float* out = (float*)d_out;                    // [new_xyz | pts_T] concatenated
    (void)in_sizes; (void)n_in; (void)out_size;

    // launch order arranged so ncu (-s 5 -c 1) profiles a gemm_one launch (#6)
    knn_kernel<<<B_ * 8, 256>>>(xyz);                                        // 1
    transpose_in<<<dim3(N_ / 32, C_ / 32, B_ / 2), dim3(32, 8)>>>(points, 0);       // 2
    transpose_in<<<dim3(N_ / 32, C_ / 32, B_ / 2), dim3(32, 8)>>>(points, B_ / 2);  // 3
    for (int i = 0; i < NBLK; ++i) {
        gemm_one<<<dim3(M_ / BM, 2), 256>>>(Wc + (size_t)i * C_ * C_,        // 4,6,8,10
                                            Wg + (size_t)i * C_ * C_);
        gather_combine<<<M_ / 8, 256>>>();                                   // 5,7,9,11
    }
    unpool_proj<<<M_ / 8, 256>>>(Wuc, Wug);
    finalize_xyz<<<M_ / 256, 256>>>(xyz, out);
    transpose_out<<<dim3(N_ / 32, C_ / 32, B_), dim3(32, 8)>>>(out + (size_t)B_ * 3 * 2 * N_);
}

// round 4
// speedup vs baseline: 1.1036x; 1.1036x over previous
#include <cuda_runtime.h>
#include <float.h>

// Problem constants
#define B_   16
#define N_   2048
#define C_   128
#define M_   (B_ * N_)          // 32768 rows
#define KNN  8
#define NBLK 4

#define ALPHA_F    0.8888888888888888f   // 8/9
#define ONEMA_F    0.1111111111111111f   // 1/9
#define WEDGE_F    0.125f                // normalized adjacency entry (deg=8 everywhere)

typedef unsigned long long u64;

__device__ __forceinline__ void ffma2(u64 &acc, u64 a, u64 b) {
    asm("fma.rn.f32x2 %0, %1, %2, %0;" : "+l"(acc) : "l"(a), "l"(b));
}
__device__ __forceinline__ float2 unpack2(u64 v) {
    float2 f; asm("mov.b64 {%0, %1}, %2;" : "=f"(f.x), "=f"(f.y) : "l"(v)); return f;
}

// ---------------- scratch (static device globals; no allocs allowed) ---------
__device__ float g_pts[M_ * C_];
__device__ float g_Ya [M_ * C_];   // epilogue-fused: pts + alpha * relu(pts)@WcT
__device__ float g_Yg [M_ * C_];
__device__ float g_Uc [M_ * 6];
__device__ float g_Ug [M_ * 6];
__device__ int   g_nbr[M_ * KNN];  // [0]=self, [1..7]=kNN (within-batch indices)

// ---------------- 1) kNN top-8 (smallest dist, stable ties) ------------------
__global__ void knn_kernel(const float* __restrict__ xyz) {
    __shared__ float sx[N_], sy[N_], sz[N_], s2[N_];
    int b = blockIdx.x >> 3;
    int qBase = (blockIdx.x & 7) * 256;
    const float* X = xyz + (size_t)b * 3 * N_;
    for (int i = threadIdx.x; i < N_; i += 256) {
        float x = X[i], y = X[N_ + i], z = X[2 * N_ + i];
        sx[i] = x; sy[i] = y; sz[i] = z;
        s2[i] = x * x + y * y + z * z;
    }
    __syncthreads();

    int q = qBase + threadIdx.x;
    float qx = sx[q], qy = sy[q], qz = sz[q], q2 = s2[q];
    float bd[KNN]; int bi[KNN];
#pragma unroll
    for (int s = 0; s < KNN; ++s) { bd[s] = FLT_MAX; bi[s] = 0x7fffffff; }

    for (int j = 0; j < N_; ++j) {
        float inner = qx * sx[j] + qy * sy[j] + qz * sz[j];
        float d = (q2 + s2[j]) - 2.0f * inner;
        if (d < bd[KNN - 1]) {                   // strict <: stable tie (lower idx wins)
            bd[KNN - 1] = d; bi[KNN - 1] = j;
#pragma unroll
            for (int s = KNN - 1; s > 0; --s) {
                if (bd[s] < bd[s - 1]) {
                    float td = bd[s]; bd[s] = bd[s - 1]; bd[s - 1] = td;
                    int   ti = bi[s]; bi[s] = bi[s - 1]; bi[s - 1] = ti;
                }
            }
        }
    }
    int* outp = g_nbr + (size_t)(b * N_ + q) * KNN;
    outp[0] = q;
#pragma unroll
    for (int s = 1; s < KNN; ++s) outp[s] = bi[s];
}

// ------- 2) transpose points (B,C,N) -> pts (B,N,C), half the batch per call -
__global__ void transpose_in(const float* __restrict__ pin, int bOff) {
    __shared__ float tile[32][33];
    int b = blockIdx.z + bOff;
    int n0 = blockIdx.x * 32, c0 = blockIdx.y * 32;
    const float* src = pin + (size_t)b * C_ * N_;
    float* dst = g_pts + (size_t)b * N_ * C_;
    for (int r = threadIdx.y; r < 32; r += 8)
        tile[r][threadIdx.x] = src[(c0 + r) * N_ + n0 + threadIdx.x];
    __syncthreads();
    for (int r = threadIdx.y; r < 32; r += 8)
        dst[(n0 + r) * C_ + c0 + threadIdx.x] = tile[threadIdx.x][r];
}

// ---------------- 3) single-matrix SGEMM via packed fma.rn.f32x2 -------------
// gridDim.y == 2:
//   y=0:  Ya = pts + ALPHA * (relu(pts) @ WcT)     (residual fused in epilogue)
//   y=1:  Yg = pts @ WgT
// BM=128, BN=128, BK=16, 256 threads, 2 CTAs/SM.
// Thread (tx,ty) computes rows ty*8..ty*8+7 and cols {tx*4..tx*4+3} u {64+tx*4..67+tx*4}.
// W-fragment loads are 16 lanes at 16B stride (256B contiguous) -> conflict-free.
#define BM 128
#define BK 16
__global__ __launch_bounds__(256, 2) void gemm_one(const float* __restrict__ Wc,
                                                   const float* __restrict__ Wg) {
    __shared__ float2 sA2[BK][BM];   // (a,a) pairs
    __shared__ float  sW [BK][C_];
    const bool doRelu = (blockIdx.y == 0);
    const float* __restrict__ W = doRelu ? Wc : Wg;
    const float* A = g_pts;
    int tid = threadIdx.x;
    int tx = tid & 15;          // cols tx*4..tx*4+3 and 64+tx*4..64+tx*4+3
    int ty = tid >> 4;          // rows ty*8 .. ty*8+7
    int row0 = blockIdx.x * BM;

    u64 acc[8][4];              // [row][0..1]=cols tx*4.., [2..3]=cols 64+tx*4..
#pragma unroll
    for (int i = 0; i < 8; ++i)
#pragma unroll
        for (int j = 0; j < 4; ++j) acc[i][j] = 0ull;

    for (int k0 = 0; k0 < C_; k0 += BK) {
        // A tile: 128x16 = 512 float4 -> 2 per thread (duplicated, relu'd if y=0)
#pragma unroll
        for (int r = 0; r < 2; ++r) {
            int idx = tid + r * 256;
            int m = idx >> 2;
            int kq = (idx & 3) * 4;
            float4 v = *(const float4*)&A[(size_t)(row0 + m) * C_ + k0 + kq];
            if (doRelu) {
                v.x = fmaxf(v.x, 0.f); v.y = fmaxf(v.y, 0.f);
                v.z = fmaxf(v.z, 0.f); v.w = fmaxf(v.w, 0.f);
            }
            sA2[kq + 0][m] = make_float2(v.x, v.x);
            sA2[kq + 1][m] = make_float2(v.y, v.y);
            sA2[kq + 2][m] = make_float2(v.z, v.z);
            sA2[kq + 3][m] = make_float2(v.w, v.w);
        }
        // W tile: 128x16 = 512 float4 -> 2 per thread
#pragma unroll
        for (int r = 0; r < 2; ++r) {
            int idx = tid + r * 256;
            int d = idx >> 2;
            int kq = (idx & 3) * 4;
            float4 vw = *(const float4*)&W[d * C_ + k0 + kq];
            sW[kq + 0][d] = vw.x; sW[kq + 1][d] = vw.y;
            sW[kq + 2][d] = vw.z; sW[kq + 3][d] = vw.w;
        }
        __syncthreads();
#pragma unroll
        for (int kk = 0; kk < BK; ++kk) {
            ulonglong2 a01 = *(const ulonglong2*)&sA2[kk][ty * 8 + 0];
            ulonglong2 a23 = *(const ulonglong2*)&sA2[kk][ty * 8 + 2];
            ulonglong2 a45 = *(const ulonglong2*)&sA2[kk][ty * 8 + 4];
            ulonglong2 a67 = *(const ulonglong2*)&sA2[kk][ty * 8 + 6];
            u64 ap[8] = {a01.x, a01.y, a23.x, a23.y, a45.x, a45.y, a67.x, a67.y};
            // conflict-free: 16B-stride across lanes (256B contiguous per load)
            ulonglong2 wq0 = *(const ulonglong2*)&sW[kk][tx * 4];
            ulonglong2 wq1 = *(const ulonglong2*)&sW[kk][64 + tx * 4];
            u64 w[4] = {wq0.x, wq0.y, wq1.x, wq1.y};
#pragma unroll
            for (int i = 0; i < 8; ++i)
#pragma unroll
                for (int j = 0; j < 4; ++j)
                    ffma2(acc[i][j], ap[i], w[j]);
        }
        __syncthreads();
    }
    // epilogue: cols tx*4 (acc[.][0..1]) and 64+tx*4 (acc[.][2..3])
    if (doRelu) {
#pragma unroll
        for (int i = 0; i < 8; ++i) {
            size_t base = (size_t)(row0 + ty * 8 + i) * C_;
            float4 p0 = *(const float4*)&g_pts[base + tx * 4];
            float4 p1 = *(const float4*)&g_pts[base + 64 + tx * 4];
            float2 c0 = unpack2(acc[i][0]), c1 = unpack2(acc[i][1]);
            float2 c2 = unpack2(acc[i][2]), c3 = unpack2(acc[i][3]);
            *(float4*)&g_Ya[base + tx * 4] =
                make_float4(p0.x + ALPHA_F * c0.x, p0.y + ALPHA_F * c0.y,
                            p0.z + ALPHA_F * c1.x, p0.w + ALPHA_F * c1.y);
            *(float4*)&g_Ya[base + 64 + tx * 4] =
                make_float4(p1.x + ALPHA_F * c2.x, p1.y + ALPHA_F * c2.y,
                            p1.z + ALPHA_F * c3.x, p1.w + ALPHA_F * c3.y);
        }
    } else {
#pragma unroll
        for (int i = 0; i < 8; ++i) {
            size_t base = (size_t)(row0 + ty * 8 + i) * C_;
            float2 g0 = unpack2(acc[i][0]), g1 = unpack2(acc[i][1]);
            float2 g2 = unpack2(acc[i][2]), g3 = unpack2(acc[i][3]);
            *(float4*)&g_Yg[base + tx * 4]      = make_float4(g0.x, g0.y, g1.x, g1.y);
            *(float4*)&g_Yg[base + 64 + tx * 4] = make_float4(g2.x, g2.y, g3.x, g3.y);
        }
    }
}

// ------- 4) gather + residual: pts = Ya + (1-a)*(adj@Yg) ---------------------
__global__ void gather_combine() {
    int node = blockIdx.x * 8 + (threadIdx.x >> 5);
    int lane = threadIdx.x & 31;
    int base = node & ~(N_ - 1);                  // batch start row
    const int* nb = g_nbr + (size_t)node * KNN;
    int c = lane * 4;
    float4 acc = make_float4(0.f, 0.f, 0.f, 0.f);
#pragma unroll
    for (int s = 0; s < KNN; ++s) {
        const float4 v = *(const float4*)&g_Yg[(size_t)(base + nb[s]) * C_ + c];
        acc.x += v.x; acc.y += v.y; acc.z += v.z; acc.w += v.w;
    }
    float4 ya = *(const float4*)&g_Ya[(size_t)node * C_ + c];
    float4 o;
    o.x = ya.x + ONEMA_F * (WEDGE_F * acc.x);
    o.y = ya.y + ONEMA_F * (WEDGE_F * acc.y);
    o.z = ya.z + ONEMA_F * (WEDGE_F * acc.z);
    o.w = ya.w + ONEMA_F * (WEDGE_F * acc.w);
    *(float4*)&g_pts[(size_t)node * C_ + c] = o;
}

// ------- 5) unpool projection: Uc = pts@WucT, Ug = pts@WugT (6 outs each) ----
__global__ void unpool_proj(const float* __restrict__ Wuc,
                            const float* __restrict__ Wug) {
    __shared__ float swc[6 * C_], swg[6 * C_];
    for (int i = threadIdx.x; i < 6 * C_; i += 256) { swc[i] = Wuc[i]; swg[i] = Wug[i]; }
    __syncthreads();
    int node = blockIdx.x * 8 + (threadIdx.x >> 5);
    int lane = threadIdx.x & 31;
    float4 p = *(const float4*)&g_pts[(size_t)node * C_ + lane * 4];
#pragma unroll
    for (int o = 0; o < 6; ++o) {
        float4 wc = *(const float4*)&swc[o * C_ + lane * 4];
        float4 wg = *(const float4*)&swg[o * C_ + lane * 4];
        float dc = p.x * wc.x + p.y * wc.y + p.z * wc.z + p.w * wc.w;
        float dg = p.x * wg.x + p.y * wg.y + p.z * wg.z + p.w * wg.w;
#pragma unroll
        for (int off = 16; off; off >>= 1) {
            dc += __shfl_xor_sync(0xffffffffu, dc, off);
            dg += __shfl_xor_sync(0xffffffffu, dg, off);
        }
        if (lane == 0) {
            g_Uc[(size_t)node * 6 + o] = dc;
            g_Ug[(size_t)node * 6 + o] = dg;
        }
    }
}

// ------- 6) finalize new_xyz: a*Uc + (1-a)*(adj@Ug), fold + reshape ----------
__global__ void finalize_xyz(const float* __restrict__ xyz, float* __restrict__ out) {
    int node = blockIdx.x * 256 + threadIdx.x;        // 0..32767
    int b = node >> 11, n = node & (N_ - 1);
    int base = node & ~(N_ - 1);
    const int* nb = g_nbr + (size_t)node * KNN;
    float g[6] = {0.f, 0.f, 0.f, 0.f, 0.f, 0.f};
#pragma unroll
    for (int s = 0; s < KNN; ++s) {
        const float* r = g_Ug + (size_t)(base + nb[s]) * 6;
#pragma unroll
        for (int o = 0; o < 6; ++o) g[o] += r[o];
    }
#pragma unroll
    for (int o = 0; o < 6; ++o) {
        float v = ALPHA_F * g_Uc[(size_t)node * 6 + o] + ONEMA_F * (WEDGE_F * g[o]);
        int cdim = o >> 1, t = o & 1;
        out[(size_t)b * 3 * (2 * N_) + cdim * (2 * N_) + t * N_ + n] =
            v + xyz[(size_t)b * 3 * N_ + cdim * N_ + n];
    }
}

// ------- 7) transpose pts (B,N,C) -> output (B,C,N) --------------------------
__global__ void transpose_out(float* __restrict__ out) {
    __shared__ float tile[32][33];
    int b = blockIdx.z;
    int n0 = blockIdx.x * 32, c0 = blockIdx.y * 32;
    const float* src = g_pts + (size_t)b * N_ * C_;
    float* dst = out + (size_t)b * C_ * N_;
    for (int r = threadIdx.y; r < 32; r += 8)
        tile[r][threadIdx.x] = src[(n0 + r) * C_ + c0 + threadIdx.x];
    __syncthreads();
    for (int r = threadIdx.y; r < 32; r += 8)
        dst[(c0 + r) * N_ + n0 + threadIdx.x] = tile[threadIdx.x][r];
}

// -----------------------------------------------------------------------------
extern "C" void kernel_launch(void* const* d_in, const int* in_sizes, int n_in,
                              void* d_out, int out_size) {
    const float* xyz    = (const float*)d_in[0];   // (16,3,2048)
    const float* points = (const float*)d_in[1];   // (16,128,2048)
    const float* Wc     = (const float*)d_in[2];   // (4,128,128)
    const float* Wg     = (const float*)d_in[3];   // (4,128,128)
    const float* Wuc    = (const float*)d_in[4];   // (6,128)
    const float* Wug    = (const float*)d_in[5];   // (6,128)
    float* out = (float*)d_out;                    // [new_xyz | pts_T] concatenated
    (void)in_sizes; (void)n_in; (void)out_size;

    // launch order arranged so ncu (-s 5 -c 1) profiles a gemm_one launch (#6)
    knn_kernel<<<B_ * 8, 256>>>(xyz);                                        // 1
    transpose_in<<<dim3(N_ / 32, C_ / 32, B_ / 2), dim3(32, 8)>>>(points, 0);       // 2
    transpose_in<<<dim3(N_ / 32, C_ / 32, B_ / 2), dim3(32, 8)>>>(points, B_ / 2);  // 3
    for (int i = 0; i < NBLK; ++i) {
        gemm_one<<<dim3(M_ / BM, 2), 256>>>(Wc + (size_t)i * C_ * C_,        // 4,6,8,10
                                            Wg + (size_t)i * C_ * C_);
        gather_combine<<<M_ / 8, 256>>>();                                   // 5,7,9,11
    }
    unpool_proj<<<M_ / 8, 256>>>(Wuc, Wug);
    finalize_xyz<<<M_ / 256, 256>>>(xyz, out);
    transpose_out<<<dim3(N_ / 32, C_ / 32, B_), dim3(32, 8)>>>(out + (size_t)B_ * 3 * 2 * N_);
}

// round 5
// speedup vs baseline: 1.2584x; 1.1402x over previous
#include <cuda_runtime.h>
#include <float.h>

// Problem constants
#define B_   16
#define N_   2048
#define C_   128
#define M_   (B_ * N_)          // 32768 rows
#define KNN  8
#define NBLK 4

#define ALPHA_F    0.8888888888888888f   // 8/9
#define ONEMA_F    0.1111111111111111f   // 1/9
#define WEDGE_F    0.125f                // normalized adjacency entry (deg=8 everywhere)

typedef unsigned long long u64;

__device__ __forceinline__ void ffma2(u64 &acc, u64 a, u64 b) {
    asm("fma.rn.f32x2 %0, %1, %2, %0;" : "+l"(acc) : "l"(a), "l"(b));
}
__device__ __forceinline__ float2 unpack2(u64 v) {
    float2 f; asm("mov.b64 {%0, %1}, %2;" : "=f"(f.x), "=f"(f.y) : "l"(v)); return f;
}
__device__ __forceinline__ u64 dup2(float a) {
    u64 r; asm("mov.b64 %0, {%1, %1};" : "=l"(r) : "f"(a)); return r;
}

// ---------------- scratch (static device globals; no allocs allowed) ---------
__device__ float g_pts[M_ * C_];
__device__ float g_Ya [M_ * C_];   // epilogue-fused: pts + alpha * relu(pts)@WcT
__device__ float g_Yg [M_ * C_];
__device__ float g_Uc [M_ * 6];
__device__ float g_Ug [M_ * 6];
__device__ int   g_nbr[M_ * KNN];  // [0]=self, [1..7]=kNN (within-batch indices)

// ---------------- 1) kNN top-8 (smallest dist, stable ties) ------------------
__global__ void knn_kernel(const float* __restrict__ xyz) {
    __shared__ float sx[N_], sy[N_], sz[N_], s2[N_];
    int b = blockIdx.x >> 3;
    int qBase = (blockIdx.x & 7) * 256;
    const float* X = xyz + (size_t)b * 3 * N_;
    for (int i = threadIdx.x; i < N_; i += 256) {
        float x = X[i], y = X[N_ + i], z = X[2 * N_ + i];
        sx[i] = x; sy[i] = y; sz[i] = z;
        s2[i] = x * x + y * y + z * z;
    }
    __syncthreads();

    int q = qBase + threadIdx.x;
    float qx = sx[q], qy = sy[q], qz = sz[q], q2 = s2[q];
    float bd[KNN]; int bi[KNN];
#pragma unroll
    for (int s = 0; s < KNN; ++s) { bd[s] = FLT_MAX; bi[s] = 0x7fffffff; }

    for (int j = 0; j < N_; ++j) {
        float inner = qx * sx[j] + qy * sy[j] + qz * sz[j];
        float d = (q2 + s2[j]) - 2.0f * inner;
        if (d < bd[KNN - 1]) {                   // strict <: stable tie (lower idx wins)
            bd[KNN - 1] = d; bi[KNN - 1] = j;
#pragma unroll
            for (int s = KNN - 1; s > 0; --s) {
                if (bd[s] < bd[s - 1]) {
                    float td = bd[s]; bd[s] = bd[s - 1]; bd[s - 1] = td;
                    int   ti = bi[s]; bi[s] = bi[s - 1]; bi[s - 1] = ti;
                }
            }
        }
    }
    int* outp = g_nbr + (size_t)(b * N_ + q) * KNN;
    outp[0] = q;
#pragma unroll
    for (int s = 1; s < KNN; ++s) outp[s] = bi[s];
}

// ------- 2) transpose points (B,C,N) -> pts (B,N,C), half the batch per call -
__global__ void transpose_in(const float* __restrict__ pin, int bOff) {
    __shared__ float tile[32][33];
    int b = blockIdx.z + bOff;
    int n0 = blockIdx.x * 32, c0 = blockIdx.y * 32;
    const float* src = pin + (size_t)b * C_ * N_;
    float* dst = g_pts + (size_t)b * N_ * C_;
    for (int r = threadIdx.y; r < 32; r += 8)
        tile[r][threadIdx.x] = src[(c0 + r) * N_ + n0 + threadIdx.x];
    __syncthreads();
    for (int r = threadIdx.y; r < 32; r += 8)
        dst[(n0 + r) * C_ + c0 + threadIdx.x] = tile[threadIdx.x][r];
}

// ---------------- 3) single-matrix SGEMM via packed fma.rn.f32x2 -------------
// gridDim.y == 2:
//   y=0:  Ya = pts + ALPHA * (relu(pts) @ WcT)     (residual fused in epilogue)
//   y=1:  Yg = pts @ WgT
// BM=128, BN=128, BK=16, 256 threads, 2 CTAs/SM.
// Double-buffered smem stages, register-staged LDG prefetch, ONE sync per iter.
// A stored un-duplicated; (a,a) packed in regs via mov.b64 (ALU is idle).
// Thread (tx,ty): rows ty*8..+7, cols {tx*4..+3} u {64+tx*4..+3}.
#define BM 128
#define BK 16
#define NK (C_ / BK)     // 8 k-tiles
__global__ __launch_bounds__(256, 2) void gemm_one(const float* __restrict__ Wc,
                                                   const float* __restrict__ Wg) {
    __shared__ float sA[2][BK][BM];   // 8KB per stage
    __shared__ float sW[2][BK][C_];   // 8KB per stage
    const bool doRelu = (blockIdx.y == 0);
    const float* __restrict__ W = doRelu ? Wc : Wg;
    const float* A = g_pts;
    int tid = threadIdx.x;
    int tx = tid & 15;          // cols tx*4..tx*4+3 and 64+tx*4..+3
    int ty = tid >> 4;          // rows ty*8 .. ty*8+7
    int row0 = blockIdx.x * BM;

    // per-thread tile-copy coordinates (2 float4 each for A and W)
    int mA0 = tid >> 2,           kqA = (tid & 3) * 4;   // + r*64 rows for r=1
    // (same pattern for W: d = idx>>2)

    u64 acc[8][4];
#pragma unroll
    for (int i = 0; i < 8; ++i)
#pragma unroll
        for (int j = 0; j < 4; ++j) acc[i][j] = 0ull;

    // ---- prologue: tile 0 -> stage 0 ----
    {
#pragma unroll
        for (int r = 0; r < 2; ++r) {
            int m = mA0 + r * 64;
            float4 v = *(const float4*)&A[(size_t)(row0 + m) * C_ + kqA];
            if (doRelu) {
                v.x = fmaxf(v.x, 0.f); v.y = fmaxf(v.y, 0.f);
                v.z = fmaxf(v.z, 0.f); v.w = fmaxf(v.w, 0.f);
            }
            sA[0][kqA + 0][m] = v.x; sA[0][kqA + 1][m] = v.y;
            sA[0][kqA + 2][m] = v.z; sA[0][kqA + 3][m] = v.w;
            int d = m;  // same decomposition
            float4 w = *(const float4*)&W[d * C_ + kqA];
            sW[0][kqA + 0][d] = w.x; sW[0][kqA + 1][d] = w.y;
            sW[0][kqA + 2][d] = w.z; sW[0][kqA + 3][d] = w.w;
        }
    }
    __syncthreads();

    int stage = 0;
    for (int t = 0; t < NK; ++t) {
        // prefetch next tile into registers (long-latency LDG overlaps compute)
        float4 nA[2], nW[2];
        if (t < NK - 1) {
            int k0n = (t + 1) * BK;
#pragma unroll
            for (int r = 0; r < 2; ++r) {
                int m = mA0 + r * 64;
                nA[r] = *(const float4*)&A[(size_t)(row0 + m) * C_ + k0n + kqA];
                nW[r] = *(const float4*)&W[m * C_ + k0n + kqA];
            }
        }
        // compute on current stage
        const float* cA = &sA[stage][0][0];
        const float* cW = &sW[stage][0][0];
#pragma unroll
        for (int kk = 0; kk < BK; ++kk) {
            float4 af0 = *(const float4*)&cA[kk * BM + ty * 8];
            float4 af1 = *(const float4*)&cA[kk * BM + ty * 8 + 4];
            u64 ap[8] = {dup2(af0.x), dup2(af0.y), dup2(af0.z), dup2(af0.w),
                         dup2(af1.x), dup2(af1.y), dup2(af1.z), dup2(af1.w)};
            ulonglong2 wq0 = *(const ulonglong2*)&cW[kk * C_ + tx * 4];
            ulonglong2 wq1 = *(const ulonglong2*)&cW[kk * C_ + 64 + tx * 4];
            u64 w[4] = {wq0.x, wq0.y, wq1.x, wq1.y};
#pragma unroll
            for (int i = 0; i < 8; ++i)
#pragma unroll
                for (int j = 0; j < 4; ++j)
                    ffma2(acc[i][j], ap[i], w[j]);
        }
        if (t < NK - 1) {
            int ns = stage ^ 1;
#pragma unroll
            for (int r = 0; r < 2; ++r) {
                int m = mA0 + r * 64;
                float4 v = nA[r];
                if (doRelu) {
                    v.x = fmaxf(v.x, 0.f); v.y = fmaxf(v.y, 0.f);
                    v.z = fmaxf(v.z, 0.f); v.w = fmaxf(v.w, 0.f);
                }
                sA[ns][kqA + 0][m] = v.x; sA[ns][kqA + 1][m] = v.y;
                sA[ns][kqA + 2][m] = v.z; sA[ns][kqA + 3][m] = v.w;
                float4 w = nW[r];
                sW[ns][kqA + 0][m] = w.x; sW[ns][kqA + 1][m] = w.y;
                sW[ns][kqA + 2][m] = w.z; sW[ns][kqA + 3][m] = w.w;
            }
            __syncthreads();   // stage ns published; stage s readers all done
            stage = ns;
        }
    }

    // epilogue: cols tx*4 (acc[.][0..1]) and 64+tx*4 (acc[.][2..3])
    if (doRelu) {
#pragma unroll
        for (int i = 0; i < 8; ++i) {
            size_t base = (size_t)(row0 + ty * 8 + i) * C_;
            float4 p0 = *(const float4*)&g_pts[base + tx * 4];
            float4 p1 = *(const float4*)&g_pts[base + 64 + tx * 4];
            float2 c0 = unpack2(acc[i][0]), c1 = unpack2(acc[i][1]);
            float2 c2 = unpack2(acc[i][2]), c3 = unpack2(acc[i][3]);
            *(float4*)&g_Ya[base + tx * 4] =
                make_float4(p0.x + ALPHA_F * c0.x, p0.y + ALPHA_F * c0.y,
                            p0.z + ALPHA_F * c1.x, p0.w + ALPHA_F * c1.y);
            *(float4*)&g_Ya[base + 64 + tx * 4] =
                make_float4(p1.x + ALPHA_F * c2.x, p1.y + ALPHA_F * c2.y,
                            p1.z + ALPHA_F * c3.x, p1.w + ALPHA_F * c3.y);
        }
    } else {
#pragma unroll
        for (int i = 0; i < 8; ++i) {
            size_t base = (size_t)(row0 + ty * 8 + i) * C_;
            float2 g0 = unpack2(acc[i][0]), g1 = unpack2(acc[i][1]);
            float2 g2 = unpack2(acc[i][2]), g3 = unpack2(acc[i][3]);
            *(float4*)&g_Yg[base + tx * 4]      = make_float4(g0.x, g0.y, g1.x, g1.y);
            *(float4*)&g_Yg[base + 64 + tx * 4] = make_float4(g2.x, g2.y, g3.x, g3.y);
        }
    }
}

// ------- 4) gather + residual: pts = Ya + (1-a)*(adj@Yg) ---------------------
__global__ void gather_combine() {
    int node = blockIdx.x * 8 + (threadIdx.x >> 5);
    int lane = threadIdx.x & 31;
    int base = node & ~(N_ - 1);                  // batch start row
    const int* nb = g_nbr + (size_t)node * KNN;
    int c = lane * 4;
    float4 acc = make_float4(0.f, 0.f, 0.f, 0.f);
#pragma unroll
    for (int s = 0; s < KNN; ++s) {
        const float4 v = *(const float4*)&g_Yg[(size_t)(base + nb[s]) * C_ + c];
        acc.x += v.x; acc.y += v.y; acc.z += v.z; acc.w += v.w;
    }
    float4 ya = *(const float4*)&g_Ya[(size_t)node * C_ + c];
    float4 o;
    o.x = ya.x + ONEMA_F * (WEDGE_F * acc.x);
    o.y = ya.y + ONEMA_F * (WEDGE_F * acc.y);
    o.z = ya.z + ONEMA_F * (WEDGE_F * acc.z);
    o.w = ya.w + ONEMA_F * (WEDGE_F * acc.w);
    *(float4*)&g_pts[(size_t)node * C_ + c] = o;
}

// ------- 5) unpool projection: Uc = pts@WucT, Ug = pts@WugT (6 outs each) ----
__global__ void unpool_proj(const float* __restrict__ Wuc,
                            const float* __restrict__ Wug) {
    __shared__ float swc[6 * C_], swg[6 * C_];
    for (int i = threadIdx.x; i < 6 * C_; i += 256) { swc[i] = Wuc[i]; swg[i] = Wug[i]; }
    __syncthreads();
    int node = blockIdx.x * 8 + (threadIdx.x >> 5);
    int lane = threadIdx.x & 31;
    float4 p = *(const float4*)&g_pts[(size_t)node * C_ + lane * 4];
#pragma unroll
    for (int o = 0; o < 6; ++o) {
        float4 wc = *(const float4*)&swc[o * C_ + lane * 4];
        float4 wg = *(const float4*)&swg[o * C_ + lane * 4];
        float dc = p.x * wc.x + p.y * wc.y + p.z * wc.z + p.w * wc.w;
        float dg = p.x * wg.x + p.y * wg.y + p.z * wg.z + p.w * wg.w;
#pragma unroll
        for (int off = 16; off; off >>= 1) {
            dc += __shfl_xor_sync(0xffffffffu, dc, off);
            dg += __shfl_xor_sync(0xffffffffu, dg, off);
        }
        if (lane == 0) {
            g_Uc[(size_t)node * 6 + o] = dc;
            g_Ug[(size_t)node * 6 + o] = dg;
        }
    }
}

// ------- 6) finalize new_xyz: a*Uc + (1-a)*(adj@Ug), fold + reshape ----------
__global__ void finalize_xyz(const float* __restrict__ xyz, float* __restrict__ out) {
    int node = blockIdx.x * 256 + threadIdx.x;        // 0..32767
    int b = node >> 11, n = node & (N_ - 1);
    int base = node & ~(N_ - 1);
    const int* nb = g_nbr + (size_t)node * KNN;
    float g[6] = {0.f, 0.f, 0.f, 0.f, 0.f, 0.f};
#pragma unroll
    for (int s = 0; s < KNN; ++s) {
        const float* r = g_Ug + (size_t)(base + nb[s]) * 6;
#pragma unroll
        for (int o = 0; o < 6; ++o) g[o] += r[o];
    }
#pragma unroll
    for (int o = 0; o < 6; ++o) {
        float v = ALPHA_F * g_Uc[(size_t)node * 6 + o] + ONEMA_F * (WEDGE_F * g[o]);
        int cdim = o >> 1, t = o & 1;
        out[(size_t)b * 3 * (2 * N_) + cdim * (2 * N_) + t * N_ + n] =
            v + xyz[(size_t)b * 3 * N_ + cdim * N_ + n];
    }
}

// ------- 7) transpose pts (B,N,C) -> output (B,C,N) --------------------------
__global__ void transpose_out(float* __restrict__ out) {
    __shared__ float tile[32][33];
    int b = blockIdx.z;
    int n0 = blockIdx.x * 32, c0 = blockIdx.y * 32;
    const float* src = g_pts + (size_t)b * N_ * C_;
    float* dst = out + (size_t)b * C_ * N_;
    for (int r = threadIdx.y; r < 32; r += 8)
        tile[r][threadIdx.x] = src[(n0 + r) * C_ + c0 + threadIdx.x];
    __syncthreads();
    for (int r = threadIdx.y; r < 32; r += 8)
        dst[(c0 + r) * N_ + n0 + threadIdx.x] = tile[threadIdx.x][r];
}

// -----------------------------------------------------------------------------
extern "C" void kernel_launch(void* const* d_in, const int* in_sizes, int n_in,
                              void* d_out, int out_size) {
    const float* xyz    = (const float*)d_in[0];   // (16,3,2048)
    const float* points = (const float*)d_in[1];   // (16,128,2048)
    const float* Wc     = (const float*)d_in[2];   // (4,128,128)
    const float* Wg     = (const float*)d_in[3];   // (4,128,128)
    const float* Wuc    = (const float*)d_in[4];   // (6,128)
    const float* Wug    = (const float*)d_in[5];   // (6,128)
    float* out = (float*)d_out;                    // [new_xyz | pts_T] concatenated
    (void)in_sizes; (void)n_in; (void)out_size;

    // launch order arranged so ncu (-s 5 -c 1) profiles a gemm_one launch (#6)
    knn_kernel<<<B_ * 8, 256>>>(xyz);                                        // 1
    transpose_in<<<dim3(N_ / 32, C_ / 32, B_ / 2), dim3(32, 8)>>>(points, 0);       // 2
    transpose_in<<<dim3(N_ / 32, C_ / 32, B_ / 2), dim3(32, 8)>>>(points, B_ / 2);  // 3
    for (int i = 0; i < NBLK; ++i) {
        gemm_one<<<dim3(M_ / BM, 2), 256>>>(Wc + (size_t)i * C_ * C_,        // 4,6,8,10
                                            Wg + (size_t)i * C_ * C_);
        gather_combine<<<M_ / 8, 256>>>();                                   // 5,7,9,11
    }
    unpool_proj<<<M_ / 8, 256>>>(Wuc, Wug);
    finalize_xyz<<<M_ / 256, 256>>>(xyz, out);
    transpose_out<<<dim3(N_ / 32, C_ / 32, B_), dim3(32, 8)>>>(out + (size_t)B_ * 3 * 2 * N_);
}

// round 8
// speedup vs baseline: 1.3096x; 1.0407x over previous
#include <cuda_runtime.h>
#include <cuda_bf16.h>
#include <float.h>

// Problem constants
#define B_   16
#define N_   2048
#define C_   128
#define M_   (B_ * N_)          // 32768 rows
#define KNN  8
#define NBLK 4

#define ALPHA_F    0.8888888888888888f   // 8/9
#define ONEMA_F    0.1111111111111111f   // 1/9
#define WEDGE_F    0.125f                // normalized adjacency entry (deg=8 everywhere)

typedef unsigned long long u64;
typedef unsigned int u32;

// ---------------- scratch (static device globals; no allocs allowed) ---------
__device__ float g_pts[M_ * C_];
__device__ float g_Ya [M_ * C_];   // epilogue-fused: pts + alpha * relu(pts)@WcT
__device__ float g_Yg [M_ * C_];
__device__ float g_Uc [M_ * 6];
__device__ float g_Ug [M_ * 6];
__device__ int   g_nbr[M_ * KNN];  // [0]=self, [1..7]=kNN (within-batch indices)
// precomputed bf16 splits of Wc/Wg: [mat][blk][128*128]
__device__ __nv_bfloat16 g_Wsh[2 * NBLK * C_ * C_];
__device__ __nv_bfloat16 g_Wsl[2 * NBLK * C_ * C_];

// ======================= mma helpers (baseline sm_80+ PTX) ===================
__device__ __forceinline__ u32 smem_u32(const void* p) {
    u32 a;
    asm("{ .reg .u64 t; cvta.to.shared.u64 t, %1; cvt.u32.u64 %0, t; }"
        : "=r"(a) : "l"(p));
    return a;
}
__device__ __forceinline__ float bfhi(float x) {
    return __bfloat162float(__float2bfloat16_rn(x));
}
// pack two fp32 -> bf16x2 (first arg -> low half / lower address)
__device__ __forceinline__ u32 packbf(float lo, float hi) {
    u32 r; asm("cvt.rn.bf16x2.f32 %0, %1, %2;" : "=r"(r) : "f"(hi), "f"(lo));
    return r;
}
__device__ __forceinline__ void ldsm_x4(u32 r[4], u32 addr) {
    asm volatile("ldmatrix.sync.aligned.m8n8.x4.shared.b16 {%0,%1,%2,%3}, [%4];"
        : "=r"(r[0]), "=r"(r[1]), "=r"(r[2]), "=r"(r[3]) : "r"(addr));
}
__device__ __forceinline__ void mma16816(float c[4], const u32 a[4], const u32 b[2]) {
    asm volatile("mma.sync.aligned.m16n8k16.row.col.f32.bf16.bf16.f32 "
        "{%0,%1,%2,%3}, {%4,%5,%6,%7}, {%8,%9}, {%0,%1,%2,%3};"
        : "+f"(c[0]), "+f"(c[1]), "+f"(c[2]), "+f"(c[3])
        : "r"(a[0]), "r"(a[1]), "r"(a[2]), "r"(a[3]), "r"(b[0]), "r"(b[1]));
}

// padded bf16 row stride (conflict-free ldmatrix: 272B -> bank step 4)
#define LDB 136
#define REG_BYTES (C_ * LDB * 2)          // 34816 per region
#define SM_AH 0
#define SM_AL REG_BYTES
#define SM_WH (2 * REG_BYTES)
#define SM_WL (3 * REG_BYTES)
#define GEMM_SMEM (4 * REG_BYTES)         // 139264 B

// ---------------- 1) kNN top-8 (smallest dist, stable ties) ------------------
__global__ void knn_kernel(const float* __restrict__ xyz) {
    __shared__ float sx[N_], sy[N_], sz[N_], s2[N_];
    int b = blockIdx.x >> 3;
    int qBase = (blockIdx.x & 7) * 256;
    const float* X = xyz + (size_t)b * 3 * N_;
    for (int i = threadIdx.x; i < N_; i += 256) {
        float x = X[i], y = X[N_ + i], z = X[2 * N_ + i];
        sx[i] = x; sy[i] = y; sz[i] = z;
        s2[i] = x * x + y * y + z * z;
    }
    __syncthreads();

    int q = qBase + threadIdx.x;
    float qx = sx[q], qy = sy[q], qz = sz[q], q2 = s2[q];
    float bd[KNN]; int bi[KNN];
#pragma unroll
    for (int s = 0; s < KNN; ++s) { bd[s] = FLT_MAX; bi[s] = 0x7fffffff; }

    for (int j = 0; j < N_; ++j) {
        float inner = qx * sx[j] + qy * sy[j] + qz * sz[j];
        float d = (q2 + s2[j]) - 2.0f * inner;
        if (d < bd[KNN - 1]) {                   // strict <: stable tie (lower idx wins)
            bd[KNN - 1] = d; bi[KNN - 1] = j;
#pragma unroll
            for (int s = KNN - 1; s > 0; --s) {
                if (bd[s] < bd[s - 1]) {
                    float td = bd[s]; bd[s] = bd[s - 1]; bd[s - 1] = td;
                    int   ti = bi[s]; bi[s] = bi[s - 1]; bi[s - 1] = ti;
                }
            }
        }
    }
    int* outp = g_nbr + (size_t)(b * N_ + q) * KNN;
    outp[0] = q;
#pragma unroll
    for (int s = 1; s < KNN; ++s) outp[s] = bi[s];
}

// ------- 1b) precompute W bf16 hi/lo splits (once per run, 64K elems/mat) ----
__global__ void prep_w(const float* __restrict__ W, int mat) {
    int i = blockIdx.x * 256 + threadIdx.x;          // 0 .. 65535
    float w = W[i];
    float h = bfhi(w);
    g_Wsh[mat * (NBLK * C_ * C_) + i] = __float2bfloat16_rn(h);
    g_Wsl[mat * (NBLK * C_ * C_) + i] = __float2bfloat16_rn(w - h);
}

// ------- 2) transpose points (B,C,N) -> pts (B,N,C), half the batch per call -
__global__ void transpose_in(const float* __restrict__ pin, int bOff) {
    __shared__ float tile[32][33];
    int b = blockIdx.z + bOff;
    int n0 = blockIdx.x * 32, c0 = blockIdx.y * 32;
    const float* src = pin + (size_t)b * C_ * N_;
    float* dst = g_pts + (size_t)b * N_ * C_;
    for (int r = threadIdx.y; r < 32; r += 8)
        tile[r][threadIdx.x] = src[(c0 + r) * N_ + n0 + threadIdx.x];
    __syncthreads();
    for (int r = threadIdx.y; r < 32; r += 8)
        dst[(n0 + r) * C_ + c0 + threadIdx.x] = tile[threadIdx.x][r];
}

// ---------------- 3) HMMA GEMM (mma.sync bf16, 2-way split) ------------------
// gridDim.y == 2:
//   y=0:  Ya = pts + ALPHA * (relu(pts) @ WcT)   (residual fused in epilogue)
//   y=1:  Yg = pts @ WgT
// One CTA = 128x128 output tile, full K=128 in smem.
// Split product: Ah*Wh + Al*Wh + Ah*Wl  (drop Al*Wl, ~3e-5 relative).
// 8 warps: warp (wm=wid&3, wn=wid>>2) owns rows wm*32..+31, cols wn*64..+63.
__global__ __launch_bounds__(256) void gemm_tc(int blk) {
    extern __shared__ char S[];
    const int mat = blockIdx.y;               // 0 = Wc/relu path, 1 = Wg
    const bool doRelu = (mat == 0);
    int t = threadIdx.x;
    int row0 = blockIdx.x * 128;
    u32 sb = smem_u32(S);

    // ---- A tile: load f32, (relu), split-convert to bf16 hi/lo in smem ----
    {
        int row = t >> 1, half = t & 1;
        const float* src = &g_pts[(size_t)(row0 + row) * C_ + half * 64];
        u32 so = (u32)(row * LDB + half * 64) * 2;
#pragma unroll
        for (int j = 0; j < 16; ++j) {
            float4 v = *(const float4*)&src[j * 4];
            if (doRelu) {
                v.x = fmaxf(v.x, 0.f); v.y = fmaxf(v.y, 0.f);
                v.z = fmaxf(v.z, 0.f); v.w = fmaxf(v.w, 0.f);
            }
            float h0 = bfhi(v.x), h1 = bfhi(v.y), h2 = bfhi(v.z), h3 = bfhi(v.w);
            *(u64*)(S + SM_AH + so + j * 8) =
                (u64)packbf(h0, h1) | ((u64)packbf(h2, h3) << 32);
            *(u64*)(S + SM_AL + so + j * 8) =
                (u64)packbf(v.x - h0, v.y - h1) | ((u64)packbf(v.z - h2, v.w - h3) << 32);
        }
    }
    // ---- W tile: copy precomputed bf16 hi/lo into padded smem ----
    {
        int row = t >> 1, half = t & 1;
        size_t gb = (size_t)(mat * NBLK + blk) * (C_ * C_) + row * C_ + half * 64;
        const uint4* wh = (const uint4*)&g_Wsh[gb];
        const uint4* wl = (const uint4*)&g_Wsl[gb];
        u32 so = (u32)(row * LDB + half * 64) * 2;
#pragma unroll
        for (int j = 0; j < 8; ++j) {           // 64 bf16 = 128B = 8 uint4
            *(uint4*)(S + SM_WH + so + j * 16) = wh[j];
            *(uint4*)(S + SM_WL + so + j * 16) = wl[j];
        }
    }
    __syncthreads();

    int wid = t >> 5, lane = t & 31;
    int wm = wid & 3, wn = wid >> 2;
    int gid = lane >> 2, tig = lane & 3;

    // ldmatrix lane-address offsets (bytes, before k-step add)
    // A x4 tiles: (rows m..+7,k0-7),(rows m+8..,k0-7),(m..,k8-15),(m+8..,k8-15)
    int arow = (lane & 7) + ((lane >> 3) & 1) * 8;
    int acol = ((lane >> 4) & 1) * 8;
    // B x4 tiles: (n..+7,k0-7),(n..+7,k8-15),(n+8..,k0-7),(n+8..,k8-15)
    int brow = (lane & 7) + ((lane >> 4) & 1) * 8;
    int bcol = ((lane >> 3) & 1) * 8;

    u32 aAh[2], aAl[2];
#pragma unroll
    for (int mt = 0; mt < 2; ++mt) {
        u32 o = (u32)((wm * 32 + mt * 16 + arow) * LDB + acol) * 2;
        aAh[mt] = sb + SM_AH + o;
        aAl[mt] = sb + SM_AL + o;
    }
    u32 aBh[4], aBl[4];
#pragma unroll
    for (int p = 0; p < 4; ++p) {
        u32 o = (u32)((wn * 64 + p * 16 + brow) * LDB + bcol) * 2;
        aBh[p] = sb + SM_WH + o;
        aBl[p] = sb + SM_WL + o;
    }

    float acc[2][8][4];
#pragma unroll
    for (int i = 0; i < 2; ++i)
#pragma unroll
        for (int j = 0; j < 8; ++j)
#pragma unroll
            for (int q = 0; q < 4; ++q) acc[i][j][q] = 0.f;

    for (int kt = 0; kt < 8; ++kt) {
        u32 kadd = kt * 32;                    // 16 bf16 cols = 32 bytes
        u32 ah0[4], ah1[4], al0[4], al1[4];
        ldsm_x4(ah0, aAh[0] + kadd); ldsm_x4(ah1, aAh[1] + kadd);
        ldsm_x4(al0, aAl[0] + kadd); ldsm_x4(al1, aAl[1] + kadd);
#pragma unroll
        for (int p = 0; p < 4; ++p) {
            u32 bh[4], bl[4];
            ldsm_x4(bh, aBh[p] + kadd);
            // hh
            mma16816(acc[0][2 * p],     ah0, bh);
            mma16816(acc[0][2 * p + 1], ah0, bh + 2);
            mma16816(acc[1][2 * p],     ah1, bh);
            mma16816(acc[1][2 * p + 1], ah1, bh + 2);
            // lh
            mma16816(acc[0][2 * p],     al0, bh);
            mma16816(acc[0][2 * p + 1], al0, bh + 2);
            mma16816(acc[1][2 * p],     al1, bh);
            mma16816(acc[1][2 * p + 1], al1, bh + 2);
            // hl
            ldsm_x4(bl, aBl[p] + kadd);
            mma16816(acc[0][2 * p],     ah0, bl);
            mma16816(acc[0][2 * p + 1], ah0, bl + 2);
            mma16816(acc[1][2 * p],     ah1, bl);
            mma16816(acc[1][2 * p + 1], ah1, bl + 2);
        }
    }

    // ---- epilogue: c0,c1 -> (row, col..col+1); c2,c3 -> (row+8, col..col+1)
#pragma unroll
    for (int mt = 0; mt < 2; ++mt) {
#pragma unroll
        for (int nt = 0; nt < 8; ++nt) {
            int r = row0 + wm * 32 + mt * 16 + gid;
            int cc = wn * 64 + nt * 8 + tig * 2;
            const float* a4 = acc[mt][nt];
            if (doRelu) {
                float2 p0 = *(const float2*)&g_pts[(size_t)r * C_ + cc];
                float2 p1 = *(const float2*)&g_pts[(size_t)(r + 8) * C_ + cc];
                *(float2*)&g_Ya[(size_t)r * C_ + cc] =
                    make_float2(p0.x + ALPHA_F * a4[0], p0.y + ALPHA_F * a4[1]);
                *(float2*)&g_Ya[(size_t)(r + 8) * C_ + cc] =
                    make_float2(p1.x + ALPHA_F * a4[2], p1.y + ALPHA_F * a4[3]);
            } else {
                *(float2*)&g_Yg[(size_t)r * C_ + cc]       = make_float2(a4[0], a4[1]);
                *(float2*)&g_Yg[(size_t)(r + 8) * C_ + cc] = make_float2(a4[2], a4[3]);
            }
        }
    }
}

// ------- 4) gather + residual: pts = Ya + (1-a)*(adj@Yg) ---------------------
__global__ void gather_combine() {
    int node = blockIdx.x * 8 + (threadIdx.x >> 5);
    int lane = threadIdx.x & 31;
    int base = node & ~(N_ - 1);                  // batch start row
    const int* nb = g_nbr + (size_t)node * KNN;
    int c = lane * 4;
    float4 acc = make_float4(0.f, 0.f, 0.f, 0.f);
#pragma unroll
    for (int s = 0; s < KNN; ++s) {
        const float4 v = *(const float4*)&g_Yg[(size_t)(base + nb[s]) * C_ + c];
        acc.x += v.x; acc.y += v.y; acc.z += v.z; acc.w += v.w;
    }
    float4 ya = *(const float4*)&g_Ya[(size_t)node * C_ + c];
    float4 o;
    o.x = ya.x + ONEMA_F * (WEDGE_F * acc.x);
    o.y = ya.y + ONEMA_F * (WEDGE_F * acc.y);
    o.z = ya.z + ONEMA_F * (WEDGE_F * acc.z);
    o.w = ya.w + ONEMA_F * (WEDGE_F * acc.w);
    *(float4*)&g_pts[(size_t)node * C_ + c] = o;
}

// ------- 5) unpool projection: Uc = pts@WucT, Ug = pts@WugT (6 outs each) ----
__global__ void unpool_proj(const float* __restrict__ Wuc,
                            const float* __restrict__ Wug) {
    __shared__ float swc[6 * C_], swg[6 * C_];
    for (int i = threadIdx.x; i < 6 * C_; i += 256) { swc[i] = Wuc[i]; swg[i] = Wug[i]; }
    __syncthreads();
    int node = blockIdx.x * 8 + (threadIdx.x >> 5);
    int lane = threadIdx.x & 31;
    float4 p = *(const float4*)&g_pts[(size_t)node * C_ + lane * 4];
#pragma unroll
    for (int o = 0; o < 6; ++o) {
        float4 wc = *(const float4*)&swc[o * C_ + lane * 4];
        float4 wg = *(const float4*)&swg[o * C_ + lane * 4];
        float dc = p.x * wc.x + p.y * wc.y + p.z * wc.z + p.w * wc.w;
        float dg = p.x * wg.x + p.y * wg.y + p.z * wg.z + p.w * wg.w;
#pragma unroll
        for (int off = 16; off; off >>= 1) {
            dc += __shfl_xor_sync(0xffffffffu, dc, off);
            dg += __shfl_xor_sync(0xffffffffu, dg, off);
        }
        if (lane == 0) {
            g_Uc[(size_t)node * 6 + o] = dc;
            g_Ug[(size_t)node * 6 + o] = dg;
        }
    }
}

// ------- 6) finalize new_xyz: a*Uc + (1-a)*(adj@Ug), fold + reshape ----------
__global__ void finalize_xyz(const float* __restrict__ xyz, float* __restrict__ out) {
    int node = blockIdx.x * 256 + threadIdx.x;        // 0..32767
    int b = node >> 11, n = node & (N_ - 1);
    int base = node & ~(N_ - 1);
    const int* nb = g_nbr + (size_t)node * KNN;
    float g[6] = {0.f, 0.f, 0.f, 0.f, 0.f, 0.f};
#pragma unroll
    for (int s = 0; s < KNN; ++s) {
        const float* r = g_Ug + (size_t)(base + nb[s]) * 6;
#pragma unroll
        for (int o = 0; o < 6; ++o) g[o] += r[o];
    }
#pragma unroll
    for (int o = 0; o < 6; ++o) {
        float v = ALPHA_F * g_Uc[(size_t)node * 6 + o] + ONEMA_F * (WEDGE_F * g[o]);
        int cdim = o >> 1, t = o & 1;
        out[(size_t)b * 3 * (2 * N_) + cdim * (2 * N_) + t * N_ + n] =
            v + xyz[(size_t)b * 3 * N_ + cdim * N_ + n];
    }
}

// ------- 7) transpose pts (B,N,C) -> output (B,C,N) --------------------------
__global__ void transpose_out(float* __restrict__ out) {
    __shared__ float tile[32][33];
    int b = blockIdx.z;
    int n0 = blockIdx.x * 32, c0 = blockIdx.y * 32;
    const float* src = g_pts + (size_t)b * N_ * C_;
    float* dst = out + (size_t)b * C_ * N_;
    for (int r = threadIdx.y; r < 32; r += 8)
        tile[r][threadIdx.x] = src[(n0 + r) * C_ + c0 + threadIdx.x];
    __syncthreads();
    for (int r = threadIdx.y; r < 32; r += 8)
        dst[(c0 + r) * N_ + n0 + threadIdx.x] = tile[threadIdx.x][r];
}

// -----------------------------------------------------------------------------
extern "C" void kernel_launch(void* const* d_in, const int* in_sizes, int n_in,
                              void* d_out, int out_size) {
    const float* xyz    = (const float*)d_in[0];   // (16,3,2048)
    const float* points = (const float*)d_in[1];   // (16,128,2048)
    const float* Wc     = (const float*)d_in[2];   // (4,128,128)
    const float* Wg     = (const float*)d_in[3];   // (4,128,128)
    const float* Wuc    = (const float*)d_in[4];   // (6,128)
    const float* Wug    = (const float*)d_in[5];   // (6,128)
    float* out = (float*)d_out;                    // [new_xyz | pts_T] concatenated
    (void)in_sizes; (void)n_in; (void)out_size;

    // host-side config (idempotent; not a stream op)
    cudaFuncSetAttribute(gemm_tc, cudaFuncAttributeMaxDynamicSharedMemorySize, GEMM_SMEM);

    // launch order: ncu (-s 5 -c 1) profiles launch idx 5 = first gemm_tc
    knn_kernel<<<B_ * 8, 256>>>(xyz);                                        // 0
    prep_w<<<256, 256>>>(Wc, 0);                                             // 1
    prep_w<<<256, 256>>>(Wg, 1);                                             // 2
    transpose_in<<<dim3(N_ / 32, C_ / 32, B_ / 2), dim3(32, 8)>>>(points, 0);       // 3
    transpose_in<<<dim3(N_ / 32, C_ / 32, B_ / 2), dim3(32, 8)>>>(points, B_ / 2);  // 4
    for (int i = 0; i < NBLK; ++i) {
        gemm_tc<<<dim3(M_ / 128, 2), 256, GEMM_SMEM>>>(i);                   // 5,7,9,11
        gather_combine<<<M_ / 8, 256>>>();                                   // 6,8,10,12
    }
    unpool_proj<<<M_ / 8, 256>>>(Wuc, Wug);
    finalize_xyz<<<M_ / 256, 256>>>(xyz, out);
    transpose_out<<<dim3(N_ / 32, C_ / 32, B_), dim3(32, 8)>>>(out + (size_t)B_ * 3 * 2 * N_);
}